// round 10
// baseline (speedup 1.0000x reference)
#include <cuda_runtime.h>
#include <cstdint>

// Problem constants
#define B_    4
#define N_    32
#define H_    28
#define W_    28
#define D_    16
#define HO    26
#define WO    26
#define O_    32
#define NI    288
#define ITERS 7

#define TPB   288            // 9 warps; thread t owns M row t
#define VST   20             // Vf stride (floats), 80B rows, 16B aligned
#define MST   36             // scaled-M stride, 144B rows, 16B aligned
#define QST   20             // qf stride

#define VF_OFF   0
#define MM_OFF   5760
#define QF_OFF   (5760 + 10368)          // 16128
#define VV_OFF   (QF_OFF + 640)          // 16768
#define RED_OFF  (VV_OFF + 32)           // 16800
#define SMEM_FLOATS (RED_OFF + 288)      // 17088
#define SMEM_BYTES  (SMEM_FLOATS * 4)    // 68352 -> 3 CTAs/SM

typedef unsigned long long u64;

__device__ __forceinline__ u64 pack2(float lo, float hi) {
    u64 d; asm("mov.b64 %0, {%1, %2};" : "=l"(d) : "f"(lo), "f"(hi)); return d;
}
__device__ __forceinline__ void unpack2(float& lo, float& hi, u64 s) {
    asm("mov.b64 {%0, %1}, %2;" : "=f"(lo), "=f"(hi) : "l"(s));
}
__device__ __forceinline__ u64 fma2(u64 a, u64 b, u64 c) {
    u64 d; asm("fma.rn.f32x2 %0, %1, %2, %3;" : "=l"(d) : "l"(a), "l"(b), "l"(c)); return d;
}
__device__ __forceinline__ u64 mul2(u64 a, u64 b) {
    u64 d; asm("mul.rn.f32x2 %0, %1, %2;" : "=l"(d) : "l"(a), "l"(b)); return d;
}
__device__ __forceinline__ u64 add2(u64 a, u64 b) {
    u64 d; asm("add.rn.f32x2 %0, %1, %2;" : "=l"(d) : "l"(a), "l"(b)); return d;
}
__device__ __forceinline__ void lds2(u64& a, u64& b, uint32_t addr) {
    asm volatile("ld.shared.v2.u64 {%0, %1}, [%2];" : "=l"(a), "=l"(b) : "r"(addr) : "memory");
}
__device__ __forceinline__ void sts2(uint32_t addr, u64 a, u64 b) {
    asm volatile("st.shared.v2.u64 [%0], {%1, %2};" :: "r"(addr), "l"(a), "l"(b) : "memory");
}
__device__ __forceinline__ float ex2f(float x) {
    float r; asm("ex2.approx.f32 %0, %1;" : "=f"(r) : "f"(x)); return r;
}

__global__ __launch_bounds__(TPB, 3) void sacaps_kernel(
    const float* __restrict__ inp,    // (4,32,28,28,16)
    const float* __restrict__ wcur,   // (3,3,32,4,4)
    const float* __restrict__ wnext,  // (32,4,4)
    const float* __restrict__ lns,    // (16,)
    const float* __restrict__ lnb,    // (16,)
    float* __restrict__ out)          // (4,32,26,26,16)
{
    extern __shared__ float sm[];
    const uint32_t sb   = (uint32_t)__cvta_generic_to_shared(sm);
    const uint32_t vf_b = sb + VF_OFF * 4;
    const uint32_t mm_b = sb + MM_OFF * 4;
    const uint32_t qf_b = sb + QF_OFF * 4;
    float* Vf  = sm + VF_OFF;
    float* qfs = sm + QF_OFF;
    float* vv  = sm + VV_OFF;
    float* red = sm + RED_OFF;

    const int t    = threadIdx.x;
    const int lane = t & 31;
    const int wid  = t >> 5;
    const int site = blockIdx.x;
    const int b    = site / (HO * WO);
    const int rem  = site - b * (HO * WO);
    const int hh   = rem / WO;
    const int ww   = rem - hh * WO;

    // ---- stage w_next * C into smem (C = log2(e)/3 folded into Q) ----
    const float C = 0.4808983469629878f;
    for (int g = t; g < 512; g += TPB) {
        int o = g >> 4, d = g & 15;
        qfs[o * QST + d] = C * wnext[g];
    }

    // ---- Phase 1: vote t: 4x4 matmul from global; row kept in regs AND stored ----
    u64 f2[8];
    {
        int n  = t / 9;
        int kl = t - n * 9;
        int k  = kl / 3, l = kl - k * 3;
        const float4* pb = (const float4*)(inp +
            ((size_t)(((b * N_ + n) * H_) + hh + k) * W_ + (ww + l)) * D_);
        float4 p0 = pb[0], p1 = pb[1], p2 = pb[2], p3 = pb[3];
        const float4* wb = (const float4*)(wcur + kl * 512 + n * 16);
        float4 w0 = wb[0], w1 = wb[1], w2 = wb[2], w3 = wb[3];
        float vx, vy, vz, vw;
        vx = p0.x*w0.x + p0.y*w1.x + p0.z*w2.x + p0.w*w3.x;
        vy = p0.x*w0.y + p0.y*w1.y + p0.z*w2.y + p0.w*w3.y;
        vz = p0.x*w0.z + p0.y*w1.z + p0.z*w2.z + p0.w*w3.z;
        vw = p0.x*w0.w + p0.y*w1.w + p0.z*w2.w + p0.w*w3.w;
        f2[0] = pack2(vx, vy); f2[1] = pack2(vz, vw);
        vx = p1.x*w0.x + p1.y*w1.x + p1.z*w2.x + p1.w*w3.x;
        vy = p1.x*w0.y + p1.y*w1.y + p1.z*w2.y + p1.w*w3.y;
        vz = p1.x*w0.z + p1.y*w1.z + p1.z*w2.z + p1.w*w3.z;
        vw = p1.x*w0.w + p1.y*w1.w + p1.z*w2.w + p1.w*w3.w;
        f2[2] = pack2(vx, vy); f2[3] = pack2(vz, vw);
        vx = p2.x*w0.x + p2.y*w1.x + p2.z*w2.x + p2.w*w3.x;
        vy = p2.x*w0.y + p2.y*w1.y + p2.z*w2.y + p2.w*w3.y;
        vz = p2.x*w0.z + p2.y*w1.z + p2.z*w2.z + p2.w*w3.z;
        vw = p2.x*w0.w + p2.y*w1.w + p2.z*w2.w + p2.w*w3.w;
        f2[4] = pack2(vx, vy); f2[5] = pack2(vz, vw);
        vx = p3.x*w0.x + p3.y*w1.x + p3.z*w2.x + p3.w*w3.x;
        vy = p3.x*w0.y + p3.y*w1.y + p3.z*w2.y + p3.w*w3.y;
        vz = p3.x*w0.z + p3.y*w1.z + p3.z*w2.z + p3.w*w3.z;
        vw = p3.x*w0.w + p3.y*w1.w + p3.z*w2.w + p3.w*w3.w;
        f2[6] = pack2(vx, vy); f2[7] = pack2(vz, vw);
        uint32_t va = vf_b + (uint32_t)(t * VST) * 4;
        sts2(va,      f2[0], f2[1]);
        sts2(va + 16, f2[2], f2[3]);
        sts2(va + 32, f2[4], f2[5]);
        sts2(va + 48, f2[6], f2[7]);
    }
    __syncthreads();   // qfs visible

    // ---- Phase 2: m[o] = exp2( dot(Vf[t], C*qf[o]) ), processed in o-pairs ----
    u64 m2[16];
    {
#pragma unroll 4
        for (int op = 0; op < 16; op++) {
            uint32_t qa = qf_b + (uint32_t)(2 * op * QST) * 4;
            uint32_t qb = qa + (uint32_t)(QST * 4);
            u64 q0, q1, q2, q3;
            // dot with q[2*op]
            lds2(q0, q1, qa);
            lds2(q2, q3, qa + 16);
            u64 aA = mul2(f2[0], q0);
            u64 aB = mul2(f2[1], q1);
            aA = fma2(f2[2], q2, aA);
            aB = fma2(f2[3], q3, aB);
            lds2(q0, q1, qa + 32);
            lds2(q2, q3, qa + 48);
            aA = fma2(f2[4], q0, aA);
            aB = fma2(f2[5], q1, aB);
            aA = fma2(f2[6], q2, aA);
            aB = fma2(f2[7], q3, aB);
            u64 da = add2(aA, aB);
            // dot with q[2*op+1]
            lds2(q0, q1, qb);
            lds2(q2, q3, qb + 16);
            u64 bA = mul2(f2[0], q0);
            u64 bB = mul2(f2[1], q1);
            bA = fma2(f2[2], q2, bA);
            bB = fma2(f2[3], q3, bB);
            lds2(q0, q1, qb + 32);
            lds2(q2, q3, qb + 48);
            bA = fma2(f2[4], q0, bA);
            bB = fma2(f2[5], q1, bB);
            bA = fma2(f2[6], q2, bA);
            bB = fma2(f2[7], q3, bB);
            u64 db = add2(bA, bB);
            // horizontal pair finish: {dot_a, dot_b} in one add2
            float dal, dah, dbl, dbh;
            unpack2(dal, dah, da);
            unpack2(dbl, dbh, db);
            u64 dsum = add2(pack2(dal, dbl), pack2(dah, dbh));
            float dl, dh; unpack2(dl, dh, dsum);
            m2[op] = pack2(ex2f(dl), ex2f(dh));
        }
    }

    // ---- Phase 3: multiplicative Sinkhorn, M register-resident (packed) ----
    float u = 0.f;
    for (int it = 0; it < ITERS; it++) {
        float s;
        if (it == 0) {
            u64 aA = add2(m2[0], m2[2]);
            u64 aB = add2(m2[1], m2[3]);
#pragma unroll
            for (int j = 4; j < 16; j += 2) {
                aA = add2(aA, m2[j]);
                aB = add2(aB, m2[j + 1]);
            }
            u64 aa = add2(aA, aB);
            float lo, hi; unpack2(lo, hi, aa);
            s = lo + hi;
        } else {
            uint32_t va = sb + VV_OFF * 4;
            u64 p0, p1, p2, p3;
            lds2(p0, p1, va);
            lds2(p2, p3, va + 16);
            u64 aA = mul2(m2[0], p0);
            u64 aB = mul2(m2[1], p1);
            aA = fma2(m2[2], p2, aA);
            aB = fma2(m2[3], p3, aB);
            lds2(p0, p1, va + 32);
            lds2(p2, p3, va + 48);
            aA = fma2(m2[4], p0, aA);
            aB = fma2(m2[5], p1, aB);
            aA = fma2(m2[6], p2, aA);
            aB = fma2(m2[7], p3, aB);
            lds2(p0, p1, va + 64);
            lds2(p2, p3, va + 80);
            aA = fma2(m2[8], p0, aA);
            aB = fma2(m2[9], p1, aB);
            aA = fma2(m2[10], p2, aA);
            aB = fma2(m2[11], p3, aB);
            lds2(p0, p1, va + 96);
            lds2(p2, p3, va + 112);
            aA = fma2(m2[12], p0, aA);
            aB = fma2(m2[13], p1, aB);
            aA = fma2(m2[14], p2, aA);
            aB = fma2(m2[15], p3, aB);
            u64 aa = add2(aA, aB);
            float lo, hi; unpack2(lo, hi, aa);
            s = lo + hi;
        }
        u = __fdividef(1.0f, s);

        // column sums via pair butterfly: lane l ends with colsum[l] partial
        u64 up = pack2(u, u);
        u64 w2[8];
#pragma unroll
        for (int j = 0; j < 8; j++) {
            u64 a = mul2(m2[j], up);
            u64 bq = mul2(m2[j + 8], up);
            u64 keep = (lane & 16) ? bq : a;
            u64 send = (lane & 16) ? a : bq;
            w2[j] = add2(keep, __shfl_xor_sync(0xffffffffu, send, 16));
        }
#pragma unroll
        for (int j = 0; j < 4; j++) {
            u64 keep = (lane & 8) ? w2[j + 4] : w2[j];
            u64 send = (lane & 8) ? w2[j] : w2[j + 4];
            w2[j] = add2(keep, __shfl_xor_sync(0xffffffffu, send, 8));
        }
#pragma unroll
        for (int j = 0; j < 2; j++) {
            u64 keep = (lane & 4) ? w2[j + 2] : w2[j];
            u64 send = (lane & 4) ? w2[j] : w2[j + 2];
            w2[j] = add2(keep, __shfl_xor_sync(0xffffffffu, send, 4));
        }
        {
            u64 keep = (lane & 2) ? w2[1] : w2[0];
            u64 send = (lane & 2) ? w2[0] : w2[1];
            w2[0] = add2(keep, __shfl_xor_sync(0xffffffffu, send, 2));
        }
        float lo, hi; unpack2(lo, hi, w2[0]);
        float kp = (lane & 1) ? hi : lo;
        float sd = (lane & 1) ? lo : hi;
        float res = kp + __shfl_xor_sync(0xffffffffu, sd, 1);
        red[wid * 32 + lane] = res;
        __syncthreads();
        if (t < 32) {
            float cs = 0.f;
#pragma unroll
            for (int g = 0; g < 9; g++) cs += red[g * 32 + t];
            vv[t] = __fdividef(1.0f, cs);
        }
        __syncthreads();
    }

    // ---- write u-prescaled M row to smem, PERMUTED layout [i][o_lo][oh] ----
    {
        float ms[32];
#pragma unroll
        for (int j = 0; j < 16; j++) unpack2(ms[2 * j], ms[2 * j + 1], m2[j]);
        uint32_t ma = mm_b + (uint32_t)(t * MST) * 4;
#pragma unroll
        for (int olo = 0; olo < 8; olo++) {
            u64 a  = pack2(u * ms[olo],      u * ms[olo + 8]);
            u64 bq = pack2(u * ms[olo + 16], u * ms[olo + 24]);
            sts2(ma + olo * 16, a, bq);
        }
    }
    // Mm rows read below belong to this warp's own lanes -> warp-local ordering suffices
    __syncwarp();

    // ---- Phase 4 stage 1: lane=(o_lo, dq); per-row reads: 1 Vf-quad + 1 Mhat-quad ----
    const int olo = lane & 7;
    const int dq  = lane >> 3;       // 0..3
    u64 acc2[8];
#pragma unroll
    for (int c = 0; c < 8; c++) acc2[c] = 0ULL;
    {
        int base = wid * 32;
        uint32_t vq = vf_b + (uint32_t)(base * VST + dq * 4) * 4;
        uint32_t mq = mm_b + (uint32_t)(base * MST) * 4 + (uint32_t)(olo * 16);
#pragma unroll 4
        for (int j = 0; j < 32; j++) {
            u64 v0, v1, mh0, mh1;
            lds2(v0, v1, vq + (uint32_t)(j * VST) * 4);
            lds2(mh0, mh1, mq + (uint32_t)(j * MST) * 4);
            float ma0, ma1, ma2, ma3;
            unpack2(ma0, ma1, mh0);
            unpack2(ma2, ma3, mh1);
            u64 b0 = pack2(ma0, ma0);
            u64 b1 = pack2(ma1, ma1);
            u64 b2 = pack2(ma2, ma2);
            u64 b3 = pack2(ma3, ma3);
            acc2[0] = fma2(b0, v0, acc2[0]);
            acc2[1] = fma2(b0, v1, acc2[1]);
            acc2[2] = fma2(b1, v0, acc2[2]);
            acc2[3] = fma2(b1, v1, acc2[3]);
            acc2[4] = fma2(b2, v0, acc2[4]);
            acc2[5] = fma2(b2, v1, acc2[5]);
            acc2[6] = fma2(b3, v0, acc2[6]);
            acc2[7] = fma2(b3, v1, acc2[7]);
        }
    }
    // hoist LN params while waiting (t<128 path uses them)
    float g0 = 0.f, g1 = 0.f, g2 = 0.f, g3 = 0.f;
    float h0 = 0.f, h1 = 0.f, h2 = 0.f, h3 = 0.f;
    if (t < 128) {
        int d0 = (t & 3) * 4;
        g0 = __ldg(lns + d0);     g1 = __ldg(lns + d0 + 1);
        g2 = __ldg(lns + d0 + 2); g3 = __ldg(lns + d0 + 3);
        h0 = __ldg(lnb + d0);     h1 = __ldg(lnb + d0 + 1);
        h2 = __ldg(lnb + d0 + 2); h3 = __ldg(lnb + d0 + 3);
    }
    // red2 region = this warp's own Vf rows; all lanes finished reading (converged loop)
    __syncwarp();
#pragma unroll
    for (int oh = 0; oh < 4; oh++) {
        int o = olo + 8 * oh;
        uint32_t ra = vf_b + (uint32_t)(((wid * 32 + o) * VST + dq * 4)) * 4;
        sts2(ra, acc2[oh * 2], acc2[oh * 2 + 1]);
    }
    __syncthreads();

    // ---- Phase 4 stage 2: combine 9 chunks, v_o/C, w_next matmul, LN, store ----
    if (t < 128) {
        int o = t >> 2, quad = t & 3;
        float4 p = {0.f, 0.f, 0.f, 0.f};
#pragma unroll
        for (int g = 0; g < 9; g++) {
            float4 c = *(const float4*)(Vf + (g * 32 + o) * VST + quad * 4);
            p.x += c.x; p.y += c.y; p.z += c.z; p.w += c.w;
        }
        // qfs holds C*w_next; compensate with vo/C  (1/C = 3*ln2)
        float vo = vv[o] * 2.0794415416798357f;
        float ax = p.x * vo, ay = p.y * vo, az = p.z * vo, aw = p.w * vo;
        const float* qq = qfs + o * QST;
        float x0 = ax*qq[0] + ay*qq[4] + az*qq[8]  + aw*qq[12];
        float x1 = ax*qq[1] + ay*qq[5] + az*qq[9]  + aw*qq[13];
        float x2 = ax*qq[2] + ay*qq[6] + az*qq[10] + aw*qq[14];
        float x3 = ax*qq[3] + ay*qq[7] + az*qq[11] + aw*qq[15];
        float s = x0 + x1 + x2 + x3;
        s += __shfl_xor_sync(0xffffffffu, s, 1);
        s += __shfl_xor_sync(0xffffffffu, s, 2);
        float mu = s * (1.0f / 16.0f);
        float e0 = x0 - mu, e1 = x1 - mu, e2 = x2 - mu, e3 = x3 - mu;
        float ss = e0*e0 + e1*e1 + e2*e2 + e3*e3;
        ss += __shfl_xor_sync(0xffffffffu, ss, 1);
        ss += __shfl_xor_sync(0xffffffffu, ss, 2);
        float rstd = rsqrtf(ss * (1.0f / 16.0f) + 1e-5f);
        int d0 = quad * 4;
        float y0 = e0 * rstd * g0 + h0;
        float y1 = e1 * rstd * g1 + h1;
        float y2 = e2 * rstd * g2 + h2;
        float y3 = e3 * rstd * g3 + h3;
        size_t oidx = ((((size_t)b * O_ + o) * HO + hh) * WO + ww) * D_ + d0;
        *(float4*)(out + oidx) = make_float4(y0, y1, y2, y3);
    }
}

extern "C" void kernel_launch(void* const* d_in, const int* in_sizes, int n_in,
                              void* d_out, int out_size)
{
    (void)in_sizes; (void)n_in; (void)out_size;
    cudaFuncSetAttribute(sacaps_kernel,
                         cudaFuncAttributeMaxDynamicSharedMemorySize, SMEM_BYTES);
    sacaps_kernel<<<B_ * HO * WO, TPB, SMEM_BYTES>>>(
        (const float*)d_in[0],   // input
        (const float*)d_in[1],   // w_current
        (const float*)d_in[2],   // w_next
        (const float*)d_in[3],   // ln_scale
        (const float*)d_in[4],   // ln_bias
        (float*)d_out);
}

// round 13
// speedup vs baseline: 1.0164x; 1.0164x over previous
#include <cuda_runtime.h>
#include <cstdint>

// Problem constants
#define B_    4
#define N_    32
#define H_    28
#define W_    28
#define D_    16
#define HO    26
#define WO    26
#define O_    32
#define NI    288
#define ITERS 7

#define TPB   288            // 9 warps; thread t owns M row t
#define VST   20             // Vf stride (floats), 80B rows, 16B aligned
#define MST   36             // scaled-M stride, 144B rows, 16B aligned
#define QST   20             // qf stride

#define VF_OFF   0
#define MM_OFF   5760
#define QF_OFF   (5760 + 10368)          // 16128
#define VV_OFF   (QF_OFF + 640)          // 16768
#define RED_OFF  (VV_OFF + 32)           // 16800
#define SMEM_FLOATS (RED_OFF + 288)      // 17088
#define SMEM_BYTES  (SMEM_FLOATS * 4)    // 68352 -> 3 CTAs/SM

typedef unsigned long long u64;

__device__ __forceinline__ u64 pack2(float lo, float hi) {
    u64 d; asm("mov.b64 %0, {%1, %2};" : "=l"(d) : "f"(lo), "f"(hi)); return d;
}
__device__ __forceinline__ void unpack2(float& lo, float& hi, u64 s) {
    asm("mov.b64 {%0, %1}, %2;" : "=f"(lo), "=f"(hi) : "l"(s));
}
__device__ __forceinline__ u64 fma2(u64 a, u64 b, u64 c) {
    u64 d; asm("fma.rn.f32x2 %0, %1, %2, %3;" : "=l"(d) : "l"(a), "l"(b), "l"(c)); return d;
}
__device__ __forceinline__ u64 mul2(u64 a, u64 b) {
    u64 d; asm("mul.rn.f32x2 %0, %1, %2;" : "=l"(d) : "l"(a), "l"(b)); return d;
}
__device__ __forceinline__ u64 add2(u64 a, u64 b) {
    u64 d; asm("add.rn.f32x2 %0, %1, %2;" : "=l"(d) : "l"(a), "l"(b)); return d;
}
__device__ __forceinline__ void lds2(u64& a, u64& b, uint32_t addr) {
    asm volatile("ld.shared.v2.u64 {%0, %1}, [%2];" : "=l"(a), "=l"(b) : "r"(addr) : "memory");
}
__device__ __forceinline__ void sts2(uint32_t addr, u64 a, u64 b) {
    asm volatile("st.shared.v2.u64 [%0], {%1, %2};" :: "r"(addr), "l"(a), "l"(b) : "memory");
}
__device__ __forceinline__ float ex2f(float x) {
    float r; asm("ex2.approx.f32 %0, %1;" : "=f"(r) : "f"(x)); return r;
}

__global__ __launch_bounds__(TPB, 3) void sacaps_kernel(
    const float* __restrict__ inp,    // (4,32,28,28,16)
    const float* __restrict__ wcur,   // (3,3,32,4,4)
    const float* __restrict__ wnext,  // (32,4,4)
    const float* __restrict__ lns,    // (16,)
    const float* __restrict__ lnb,    // (16,)
    float* __restrict__ out)          // (4,32,26,26,16)
{
    extern __shared__ float sm[];
    const uint32_t sb   = (uint32_t)__cvta_generic_to_shared(sm);
    const uint32_t vf_b = sb + VF_OFF * 4;
    const uint32_t mm_b = sb + MM_OFF * 4;
    const uint32_t qf_b = sb + QF_OFF * 4;
    float* Vf  = sm + VF_OFF;
    float* qfs = sm + QF_OFF;
    float* vv  = sm + VV_OFF;
    float* red = sm + RED_OFF;

    const int t    = threadIdx.x;
    const int lane = t & 31;
    const int wid  = t >> 5;
    const int site = blockIdx.x;
    const int b    = site / (HO * WO);
    const int rem  = site - b * (HO * WO);
    const int hh   = rem / WO;
    const int ww   = rem - hh * WO;

    // ---- stage w_next * C into smem (C = log2(e)/3 folded into Q) ----
    const float C = 0.4808983469629878f;
    for (int g = t; g < 512; g += TPB) {
        int o = g >> 4, d = g & 15;
        qfs[o * QST + d] = C * wnext[g];
    }

    // ---- Phase 1: vote t: 4x4 matmul from global; row kept in regs AND stored ----
    u64 f2[8];
    {
        int n  = t / 9;
        int kl = t - n * 9;
        int k  = kl / 3, l = kl - k * 3;
        const float4* pb = (const float4*)(inp +
            ((size_t)(((b * N_ + n) * H_) + hh + k) * W_ + (ww + l)) * D_);
        float4 p0 = pb[0], p1 = pb[1], p2 = pb[2], p3 = pb[3];
        const float4* wb = (const float4*)(wcur + kl * 512 + n * 16);
        float4 w0 = wb[0], w1 = wb[1], w2 = wb[2], w3 = wb[3];
        float vx, vy, vz, vw;
        vx = p0.x*w0.x + p0.y*w1.x + p0.z*w2.x + p0.w*w3.x;
        vy = p0.x*w0.y + p0.y*w1.y + p0.z*w2.y + p0.w*w3.y;
        vz = p0.x*w0.z + p0.y*w1.z + p0.z*w2.z + p0.w*w3.z;
        vw = p0.x*w0.w + p0.y*w1.w + p0.z*w2.w + p0.w*w3.w;
        f2[0] = pack2(vx, vy); f2[1] = pack2(vz, vw);
        vx = p1.x*w0.x + p1.y*w1.x + p1.z*w2.x + p1.w*w3.x;
        vy = p1.x*w0.y + p1.y*w1.y + p1.z*w2.y + p1.w*w3.y;
        vz = p1.x*w0.z + p1.y*w1.z + p1.z*w2.z + p1.w*w3.z;
        vw = p1.x*w0.w + p1.y*w1.w + p1.z*w2.w + p1.w*w3.w;
        f2[2] = pack2(vx, vy); f2[3] = pack2(vz, vw);
        vx = p2.x*w0.x + p2.y*w1.x + p2.z*w2.x + p2.w*w3.x;
        vy = p2.x*w0.y + p2.y*w1.y + p2.z*w2.y + p2.w*w3.y;
        vz = p2.x*w0.z + p2.y*w1.z + p2.z*w2.z + p2.w*w3.z;
        vw = p2.x*w0.w + p2.y*w1.w + p2.z*w2.w + p2.w*w3.w;
        f2[4] = pack2(vx, vy); f2[5] = pack2(vz, vw);
        vx = p3.x*w0.x + p3.y*w1.x + p3.z*w2.x + p3.w*w3.x;
        vy = p3.x*w0.y + p3.y*w1.y + p3.z*w2.y + p3.w*w3.y;
        vz = p3.x*w0.z + p3.y*w1.z + p3.z*w2.z + p3.w*w3.z;
        vw = p3.x*w0.w + p3.y*w1.w + p3.z*w2.w + p3.w*w3.w;
        f2[6] = pack2(vx, vy); f2[7] = pack2(vz, vw);
        uint32_t va = vf_b + (uint32_t)(t * VST) * 4;
        sts2(va,      f2[0], f2[1]);
        sts2(va + 16, f2[2], f2[3]);
        sts2(va + 32, f2[4], f2[5]);
        sts2(va + 48, f2[6], f2[7]);
    }
    __syncthreads();   // qfs visible

    // ---- Phase 2: m[o] = exp2( dot(Vf[t], C*qf[o]) )  (R9 per-o form) ----
    u64 m2[16];
    {
        float mlo = 0.f;
#pragma unroll
        for (int o = 0; o < 32; o++) {
            uint32_t qa = qf_b + (uint32_t)(o * QST) * 4;
            u64 q0, q1, q2, q3;
            lds2(q0, q1, qa);
            lds2(q2, q3, qa + 16);
            u64 aA = mul2(f2[0], q0);
            u64 aB = mul2(f2[1], q1);
            aA = fma2(f2[2], q2, aA);
            aB = fma2(f2[3], q3, aB);
            lds2(q0, q1, qa + 32);
            lds2(q2, q3, qa + 48);
            aA = fma2(f2[4], q0, aA);
            aB = fma2(f2[5], q1, aB);
            aA = fma2(f2[6], q2, aA);
            aB = fma2(f2[7], q3, aB);
            u64 aa = add2(aA, aB);
            float lo, hi; unpack2(lo, hi, aa);
            float val = ex2f(lo + hi);
            if (o & 1) m2[o >> 1] = pack2(mlo, val); else mlo = val;
        }
    }

    // ---- Phase 3: multiplicative Sinkhorn, M register-resident (packed) ----
    float u = 0.f;
    for (int it = 0; it < ITERS; it++) {
        float s;
        if (it == 0) {
            u64 aA = add2(m2[0], m2[2]);
            u64 aB = add2(m2[1], m2[3]);
#pragma unroll
            for (int j = 4; j < 16; j += 2) {
                aA = add2(aA, m2[j]);
                aB = add2(aB, m2[j + 1]);
            }
            u64 aa = add2(aA, aB);
            float lo, hi; unpack2(lo, hi, aa);
            s = lo + hi;
        } else {
            uint32_t va = sb + VV_OFF * 4;
            u64 p0, p1, p2, p3;
            lds2(p0, p1, va);
            lds2(p2, p3, va + 16);
            u64 aA = mul2(m2[0], p0);
            u64 aB = mul2(m2[1], p1);
            aA = fma2(m2[2], p2, aA);
            aB = fma2(m2[3], p3, aB);
            lds2(p0, p1, va + 32);
            lds2(p2, p3, va + 48);
            aA = fma2(m2[4], p0, aA);
            aB = fma2(m2[5], p1, aB);
            aA = fma2(m2[6], p2, aA);
            aB = fma2(m2[7], p3, aB);
            lds2(p0, p1, va + 64);
            lds2(p2, p3, va + 80);
            aA = fma2(m2[8], p0, aA);
            aB = fma2(m2[9], p1, aB);
            aA = fma2(m2[10], p2, aA);
            aB = fma2(m2[11], p3, aB);
            lds2(p0, p1, va + 96);
            lds2(p2, p3, va + 112);
            aA = fma2(m2[12], p0, aA);
            aB = fma2(m2[13], p1, aB);
            aA = fma2(m2[14], p2, aA);
            aB = fma2(m2[15], p3, aB);
            u64 aa = add2(aA, aB);
            float lo, hi; unpack2(lo, hi, aa);
            s = lo + hi;
        }
        u = __fdividef(1.0f, s);

        // column sums via pair butterfly: lane l ends with colsum[l] partial
        u64 up = pack2(u, u);
        u64 w2[8];
#pragma unroll
        for (int j = 0; j < 8; j++) {
            u64 a = mul2(m2[j], up);
            u64 bq = mul2(m2[j + 8], up);
            u64 keep = (lane & 16) ? bq : a;
            u64 send = (lane & 16) ? a : bq;
            w2[j] = add2(keep, __shfl_xor_sync(0xffffffffu, send, 16));
        }
#pragma unroll
        for (int j = 0; j < 4; j++) {
            u64 keep = (lane & 8) ? w2[j + 4] : w2[j];
            u64 send = (lane & 8) ? w2[j] : w2[j + 4];
            w2[j] = add2(keep, __shfl_xor_sync(0xffffffffu, send, 8));
        }
#pragma unroll
        for (int j = 0; j < 2; j++) {
            u64 keep = (lane & 4) ? w2[j + 2] : w2[j];
            u64 send = (lane & 4) ? w2[j] : w2[j + 2];
            w2[j] = add2(keep, __shfl_xor_sync(0xffffffffu, send, 4));
        }
        {
            u64 keep = (lane & 2) ? w2[1] : w2[0];
            u64 send = (lane & 2) ? w2[0] : w2[1];
            w2[0] = add2(keep, __shfl_xor_sync(0xffffffffu, send, 2));
        }
        float lo, hi; unpack2(lo, hi, w2[0]);
        float kp = (lane & 1) ? hi : lo;
        float sd = (lane & 1) ? lo : hi;
        float res = kp + __shfl_xor_sync(0xffffffffu, sd, 1);
        red[wid * 32 + lane] = res;
        __syncthreads();
        if (t < 32) {
            float cs = 0.f;
#pragma unroll
            for (int g = 0; g < 9; g++) cs += red[g * 32 + t];
            vv[t] = __fdividef(1.0f, cs);
        }
        __syncthreads();
    }

    // ---- write u-prescaled M row to smem, PERMUTED layout [i][o_lo][oh] ----
    {
        float ms[32];
#pragma unroll
        for (int j = 0; j < 16; j++) unpack2(ms[2 * j], ms[2 * j + 1], m2[j]);
        uint32_t ma = mm_b + (uint32_t)(t * MST) * 4;
#pragma unroll
        for (int olo = 0; olo < 8; olo++) {
            u64 a  = pack2(u * ms[olo],      u * ms[olo + 8]);
            u64 bq = pack2(u * ms[olo + 16], u * ms[olo + 24]);
            sts2(ma + olo * 16, a, bq);
        }
    }
    // Mm rows read below belong to this warp's own lanes -> warp-local ordering suffices
    __syncwarp();

    // ---- Phase 4 stage 1: lane=(o_lo, dq); per-row reads: 1 Vf-quad + 1 Mhat-quad ----
    const int olo = lane & 7;
    const int dq  = lane >> 3;       // 0..3
    u64 acc2[8];
#pragma unroll
    for (int c = 0; c < 8; c++) acc2[c] = 0ULL;
    {
        int base = wid * 32;
        uint32_t vq = vf_b + (uint32_t)(base * VST + dq * 4) * 4;
        uint32_t mq = mm_b + (uint32_t)(base * MST) * 4 + (uint32_t)(olo * 16);
#pragma unroll 4
        for (int j = 0; j < 32; j++) {
            u64 v0, v1, mh0, mh1;
            lds2(v0, v1, vq + (uint32_t)(j * VST) * 4);
            lds2(mh0, mh1, mq + (uint32_t)(j * MST) * 4);
            float ma0, ma1, ma2, ma3;
            unpack2(ma0, ma1, mh0);
            unpack2(ma2, ma3, mh1);
            u64 b0 = pack2(ma0, ma0);
            u64 b1 = pack2(ma1, ma1);
            u64 b2 = pack2(ma2, ma2);
            u64 b3 = pack2(ma3, ma3);
            acc2[0] = fma2(b0, v0, acc2[0]);
            acc2[1] = fma2(b0, v1, acc2[1]);
            acc2[2] = fma2(b1, v0, acc2[2]);
            acc2[3] = fma2(b1, v1, acc2[3]);
            acc2[4] = fma2(b2, v0, acc2[4]);
            acc2[5] = fma2(b2, v1, acc2[5]);
            acc2[6] = fma2(b3, v0, acc2[6]);
            acc2[7] = fma2(b3, v1, acc2[7]);
        }
    }
    // hoist LN params while waiting (t<128 path uses them)
    float g0 = 0.f, g1 = 0.f, g2 = 0.f, g3 = 0.f;
    float h0 = 0.f, h1 = 0.f, h2 = 0.f, h3 = 0.f;
    if (t < 128) {
        int d0 = (t & 3) * 4;
        g0 = __ldg(lns + d0);     g1 = __ldg(lns + d0 + 1);
        g2 = __ldg(lns + d0 + 2); g3 = __ldg(lns + d0 + 3);
        h0 = __ldg(lnb + d0);     h1 = __ldg(lnb + d0 + 1);
        h2 = __ldg(lnb + d0 + 2); h3 = __ldg(lnb + d0 + 3);
    }
    // red2 region = this warp's own Vf rows; all lanes finished reading
    __syncwarp();
#pragma unroll
    for (int oh = 0; oh < 4; oh++) {
        int o = olo + 8 * oh;
        uint32_t ra = vf_b + (uint32_t)(((wid * 32 + o) * VST + dq * 4)) * 4;
        sts2(ra, acc2[oh * 2], acc2[oh * 2 + 1]);
    }
    __syncthreads();

    // ---- Phase 4 stage 2: combine 9 chunks, v_o/C, w_next matmul, LN, store ----
    if (t < 128) {
        int o = t >> 2, quad = t & 3;
        float4 p = {0.f, 0.f, 0.f, 0.f};
#pragma unroll
        for (int g = 0; g < 9; g++) {
            float4 c = *(const float4*)(Vf + (g * 32 + o) * VST + quad * 4);
            p.x += c.x; p.y += c.y; p.z += c.z; p.w += c.w;
        }
        // qfs holds C*w_next; compensate with vo/C  (1/C = 3*ln2)
        float vo = vv[o] * 2.0794415416798357f;
        float ax = p.x * vo, ay = p.y * vo, az = p.z * vo, aw = p.w * vo;
        const float* qq = qfs + o * QST;
        float x0 = ax*qq[0] + ay*qq[4] + az*qq[8]  + aw*qq[12];
        float x1 = ax*qq[1] + ay*qq[5] + az*qq[9]  + aw*qq[13];
        float x2 = ax*qq[2] + ay*qq[6] + az*qq[10] + aw*qq[14];
        float x3 = ax*qq[3] + ay*qq[7] + az*qq[11] + aw*qq[15];
        float s = x0 + x1 + x2 + x3;
        s += __shfl_xor_sync(0xffffffffu, s, 1);
        s += __shfl_xor_sync(0xffffffffu, s, 2);
        float mu = s * (1.0f / 16.0f);
        float e0 = x0 - mu, e1 = x1 - mu, e2 = x2 - mu, e3 = x3 - mu;
        float ss = e0*e0 + e1*e1 + e2*e2 + e3*e3;
        ss += __shfl_xor_sync(0xffffffffu, ss, 1);
        ss += __shfl_xor_sync(0xffffffffu, ss, 2);
        float rstd = rsqrtf(ss * (1.0f / 16.0f) + 1e-5f);
        int d0 = quad * 4;
        float y0 = e0 * rstd * g0 + h0;
        float y1 = e1 * rstd * g1 + h1;
        float y2 = e2 * rstd * g2 + h2;
        float y3 = e3 * rstd * g3 + h3;
        size_t oidx = ((((size_t)b * O_ + o) * HO + hh) * WO + ww) * D_ + d0;
        *(float4*)(out + oidx) = make_float4(y0, y1, y2, y3);
    }
}

extern "C" void kernel_launch(void* const* d_in, const int* in_sizes, int n_in,
                              void* d_out, int out_size)
{
    (void)in_sizes; (void)n_in; (void)out_size;
    cudaFuncSetAttribute(sacaps_kernel,
                         cudaFuncAttributeMaxDynamicSharedMemorySize, SMEM_BYTES);
    sacaps_kernel<<<B_ * HO * WO, TPB, SMEM_BYTES>>>(
        (const float*)d_in[0],   // input
        (const float*)d_in[1],   // w_current
        (const float*)d_in[2],   // w_next
        (const float*)d_in[3],   // ln_scale
        (const float*)d_in[4],   // ln_bias
        (float*)d_out);
}